// round 3
// baseline (speedup 1.0000x reference)
#include <cuda_runtime.h>
#include <cuda_bf16.h>

// Problem constants (from reference): B=128, T=200, V=10, F=256
#define V 10
#define VV 100
#define F 256
#define F4 64            // F/4
#define ROW4 640         // V*F/4 float4 per graph
#define NTHREADS 128

// combined degree-embedding table: comb[d][f] = emb_in[d,f] + emb_out[d,f], d in [0,10)
__device__ float g_comb[V * F];

__global__ void comb_kernel(const float* __restrict__ emb_in,
                            const float* __restrict__ emb_out)
{
    int t = blockIdx.x * blockDim.x + threadIdx.x;   // 0..2559
    if (t < V * F)
        g_comb[t] = emb_in[t] + emb_out[t];          // rows 0..9 are contiguous at front
}

__global__ __launch_bounds__(NTHREADS, 12)
void graph_embed_kernel(const float* __restrict__ end_output,
                        const float* __restrict__ S,
                        const float* __restrict__ mul,
                        const float* __restrict__ bias,
                        const float* __restrict__ means,
                        const float* __restrict__ stds,
                        const float* __restrict__ emb3,
                        const float* __restrict__ emb4,
                        float* __restrict__ out,        // outputs part
                        float* __restrict__ out_att)    // atten_bias part
{
    const int g   = blockIdx.x;      // graph index in [0, B*T)
    const int tid = threadIdx.x;

    __shared__ float ds[VV];         // symmetrized S, then FW dist (in-place)
    __shared__ int   Dsh[V];
    __shared__ int   si[VV], ei[VV];

    const float* Sg = S + (size_t)g * VV;

    // ---- prologue (all threads): symmetrize + degree ----
    if (tid < VV) {
        int ii = tid / V, jj = tid % V;
        ds[tid] = fminf(Sg[tid], Sg[jj * V + ii]);
    }
    __syncthreads();
    if (tid < V) {
        float dsum = 0.0f;
        #pragma unroll
        for (int ii = 0; ii < V; ii++) dsum += ds[ii * V + tid];
        Dsh[tid] = (int)dsum;   // trunc toward zero, dsum >= 0
    }
    __syncthreads();

    if (tid < 32) {
        // ================= warp 0: full graph pipeline =================
        const int lane = tid;
        int   ii[4], jj[4];
        bool  act[4];
        float ef[4], spv[4], dsown[4];
        const float a = sqrtf(2.0f * 3.14159f);   // PI as written in the source

        #pragma unroll
        for (int r = 0; r < 4; r++) {
            int e = lane + 32 * r;
            act[r] = (e < VV);
            int e2 = act[r] ? e : 0;
            ii[r] = e2 / V; jj[r] = e2 % V;
            spv[r] = 0.0f;
            // edge_feature = tanh(sigmoid(gauss(S@mul + bias)))
            float x = __ldg(&bias[e2]);
            #pragma unroll
            for (int m = 0; m < V; m++)
                x += ds[ii[r] * V + m] * __ldg(&mul[m * V + jj[r]]);
            float sd = __ldg(&stds[jj[r]]);
            float z  = (x - __ldg(&means[jj[r]])) / sd;
            float tmp = expf(-0.5f * z * z) / (a * sd);
            float sg  = 1.0f / (1.0f + expf(-tmp));
            ef[r] = tanhf(sg);
            dsown[r] = ds[e2];
        }
        __syncwarp();

        // Floyd-Warshall with update-indicator accumulation (warp-only sync)
        #pragma unroll
        for (int k = 0; k < V; k++) {
            float dik[4], dkj[4];
            #pragma unroll
            for (int r = 0; r < 4; r++) {
                dik[r] = ds[ii[r] * V + k];
                dkj[r] = ds[k * V + jj[r]];
            }
            __syncwarp();
            #pragma unroll
            for (int r = 0; r < 4; r++) {
                if (act[r]) {
                    float temp = dik[r] + dkj[r];
                    if (temp < dsown[r]) {       // == (new != dist)
                        dsown[r] = temp;
                        ds[lane + 32 * r] = temp;
                        spv[r] += ef[r];
                    }
                }
            }
            __syncwarp();
        }

        // integer indices
        #pragma unroll
        for (int r = 0; r < 4; r++) {
            if (act[r]) {
                int Si = (int)dsown[r]; Si = min(max(Si, 0), V - 1);
                int Ei = (int)spv[r];   Ei = min(max(Ei, 0), V - 1);
                si[lane + 32 * r] = Si;
                ei[lane + 32 * r] = Ei;
            }
        }
        __syncwarp();

        // atten_bias[g, i, c] = sum_j ( emb3[si[i,j], c] + emb4[ei[i,j], c] )
        #pragma unroll
        for (int r = 0; r < 4; r++) {
            int o = lane + 32 * r;
            if (o < VV) {
                int i2 = o / V, c = o % V;
                float acc = 0.0f;
                #pragma unroll
                for (int j2 = 0; j2 < V; j2++) {
                    acc += __ldg(&emb3[si[i2 * V + j2] * V + c]);
                    acc += __ldg(&emb4[ei[i2 * V + j2] * V + c]);
                }
                out_att[(size_t)g * VV + o] = acc;
            }
        }
    } else {
        // ============ warps 1-3: stream outputs = end_output + comb[D] ============
        const int t = tid - 32;                      // 0..95
        const float4* eo4   = (const float4*)(end_output + (size_t)g * (V * F));
        float4*       o4    = (float4*)(out + (size_t)g * (V * F));
        const float4* cmb4  = (const float4*)g_comb;
        #pragma unroll
        for (int it = 0; it < 7; it++) {
            int idx = t + it * 96;                   // 0..639
            if (idx < ROW4) {
                int v   = idx >> 6;                  // /F4
                int f4  = idx & (F4 - 1);
                int d   = Dsh[v];
                float4 e = __ldcs(&eo4[idx]);        // evict-first: no L1 reuse
                float4 c = cmb4[d * F4 + f4];        // L1-resident 10KB table
                float4 r;
                r.x = e.x + c.x; r.y = e.y + c.y;
                r.z = e.z + c.z; r.w = e.w + c.w;
                __stcs(&o4[idx], r);
            }
        }
    }
}

extern "C" void kernel_launch(void* const* d_in, const int* in_sizes, int n_in,
                              void* d_out, int out_size)
{
    const float* end_output = (const float*)d_in[0];   // (B,T,V,F)
    const float* S          = (const float*)d_in[1];   // (B,T,V,V)
    const float* mul_       = (const float*)d_in[2];   // (V,V)
    const float* bias_      = (const float*)d_in[3];   // (V,V)
    const float* means_     = (const float*)d_in[4];   // (1,V)
    const float* stds_      = (const float*)d_in[5];   // (1,V)
    const float* emb_in_    = (const float*)d_in[6];   // (F,F)
    const float* emb_out_   = (const float*)d_in[7];   // (F,F)
    const float* emb3_      = (const float*)d_in[8];   // (V,V)
    const float* emb4_      = (const float*)d_in[9];   // (V,V)

    float* out = (float*)d_out;
    const int graphs = in_sizes[1] / VV;               // B*T
    float* out_att = out + (size_t)in_sizes[0];        // atten_bias after outputs

    comb_kernel<<<V, F>>>(emb_in_, emb_out_);
    graph_embed_kernel<<<graphs, NTHREADS>>>(
        end_output, S, mul_, bias_, means_, stds_,
        emb3_, emb4_, out, out_att);
}

// round 4
// speedup vs baseline: 1.2159x; 1.2159x over previous
#include <cuda_runtime.h>
#include <cuda_bf16.h>

// Problem constants (from reference): B=128, T=200, V=10, F=256
#define V 10
#define VV 100
#define F 256
#define F4 64              // F/4 float4 per row
#define GPF4 640           // V*F/4 float4 per graph
#define NT 256

#define GPS 4              // graphs per streaming block
#define GPG 8              // graphs per graph block (1 per warp)

// combined degree-embedding table: comb[d][f] = emb_in[d,f] + emb_out[d,f], d in [0,10)
__device__ float g_comb[V * F];

__global__ void comb_kernel(const float* __restrict__ emb_in,
                            const float* __restrict__ emb_out)
{
    int t = blockIdx.x * blockDim.x + threadIdx.x;   // 0..2559
    if (t < V * F)
        g_comb[t] = emb_in[t] + emb_out[t];
}

__global__ __launch_bounds__(NT, 6)
void graph_embed_kernel(const float* __restrict__ end_output,
                        const float* __restrict__ S,
                        const float* __restrict__ mul,
                        const float* __restrict__ bias,
                        const float* __restrict__ means,
                        const float* __restrict__ stds,
                        const float* __restrict__ emb3,
                        const float* __restrict__ emb4,
                        float* __restrict__ out,
                        float* __restrict__ out_att,
                        int graphs, int nsb, int ngb, int interleave)
{
    const int bid = blockIdx.x;
    const int tid = threadIdx.x;

    // role mapping: interleaved 2 stream : 1 graph when shapes allow
    int role, rbid;
    if (interleave) {
        if ((bid % 3) == 2) { role = 1; rbid = bid / 3; }
        else                { role = 0; rbid = (bid / 3) * 2 + (bid % 3); }
    } else {
        if (bid < nsb) { role = 0; rbid = bid; }
        else           { role = 1; rbid = bid - nsb; }
    }

    if (role == 0) {
        // ================= STREAMING BLOCK: 4 graphs =================
        __shared__ float ssh[GPS * VV];
        __shared__ int   Dsh[GPS * V];

        const int g0 = rbid * GPS;
        const float* Sg = S + (size_t)g0 * VV;
        int nloc = min(GPS, graphs - g0) * VV;          // active S elements
        for (int u = tid; u < nloc; u += NT)
            ssh[u] = Sg[u];
        __syncthreads();
        if (tid < GPS * V) {
            int l = tid / V, v = tid % V;
            if (g0 + l < graphs) {
                const float* sl = ssh + l * VV;
                float dsum = 0.0f;
                #pragma unroll
                for (int ii = 0; ii < V; ii++)
                    dsum += fminf(sl[ii * V + v], sl[v * V + ii]);
                Dsh[tid] = (int)dsum;                   // trunc toward zero, >=0
            }
        }
        __syncthreads();

        const float4* eo4  = (const float4*)(end_output + (size_t)g0 * (V * F));
        float4*       o4   = (float4*)(out + (size_t)g0 * (V * F));
        const float4* cmb4 = (const float4*)g_comb;
        const int nf4 = min(GPS, graphs - g0) * GPF4;
        #pragma unroll
        for (int it = 0; it < GPS * GPF4 / NT; it++) {
            int idx = tid + it * NT;                    // 0..2559
            if (idx < nf4) {
                int vrow = idx >> 6;                    // 0..39
                int f4   = idx & (F4 - 1);
                int d    = Dsh[vrow];
                float4 e = __ldcs(&eo4[idx]);           // evict-first streaming
                float4 c = cmb4[d * F4 + f4];           // L1-resident 10KB
                float4 r;
                r.x = e.x + c.x; r.y = e.y + c.y;
                r.z = e.z + c.z; r.w = e.w + c.w;
                __stcs(&o4[idx], r);
            }
        }
    } else {
        // ================= GRAPH BLOCK: 8 graphs, 1 per warp =================
        __shared__ float dsm[GPG][VV];
        __shared__ short sim[GPG][VV], eim[GPG][VV];

        const int w    = tid >> 5;
        const int lane = tid & 31;
        const int g    = rbid * GPG + w;
        if (g < graphs) {
            float* ds = dsm[w];
            const float* Sg = S + (size_t)g * VV;

            // symmetrize into per-warp shared
            #pragma unroll
            for (int r = 0; r < 4; r++) {
                int e = lane + 32 * r;
                if (e < VV) {
                    int ii = e / V, jj = e % V;
                    ds[e] = fminf(__ldg(&Sg[e]), __ldg(&Sg[jj * V + ii]));
                }
            }
            __syncwarp();

            int   iiA[4], jjA[4];
            bool  act[4];
            float ef[4], spv[4], dsown[4];
            const float a = sqrtf(2.0f * 3.14159f);     // PI as written in source

            #pragma unroll
            for (int r = 0; r < 4; r++) {
                int e = lane + 32 * r;
                act[r] = (e < VV);
                int e2 = act[r] ? e : 0;
                iiA[r] = e2 / V; jjA[r] = e2 % V;
                spv[r] = 0.0f;
                float x = __ldg(&bias[e2]);
                #pragma unroll
                for (int m = 0; m < V; m++)
                    x += ds[iiA[r] * V + m] * __ldg(&mul[m * V + jjA[r]]);
                float sd = __ldg(&stds[jjA[r]]);
                float z  = (x - __ldg(&means[jjA[r]])) / sd;
                float tmp = expf(-0.5f * z * z) / (a * sd);
                float sg  = 1.0f / (1.0f + expf(-tmp));
                ef[r] = tanhf(sg);
                dsown[r] = ds[e2];
            }
            __syncwarp();

            // Floyd-Warshall with update-indicator accumulation
            #pragma unroll
            for (int k = 0; k < V; k++) {
                float dik[4], dkj[4];
                #pragma unroll
                for (int r = 0; r < 4; r++) {
                    dik[r] = ds[iiA[r] * V + k];
                    dkj[r] = ds[k * V + jjA[r]];
                }
                __syncwarp();
                #pragma unroll
                for (int r = 0; r < 4; r++) {
                    if (act[r]) {
                        float temp = dik[r] + dkj[r];
                        if (temp < dsown[r]) {          // == (new != dist)
                            dsown[r] = temp;
                            ds[lane + 32 * r] = temp;
                            spv[r] += ef[r];
                        }
                    }
                }
                __syncwarp();
            }

            #pragma unroll
            for (int r = 0; r < 4; r++) {
                if (act[r]) {
                    int Si = (int)dsown[r]; Si = min(max(Si, 0), V - 1);
                    int Ei = (int)spv[r];   Ei = min(max(Ei, 0), V - 1);
                    sim[w][lane + 32 * r] = (short)Si;
                    eim[w][lane + 32 * r] = (short)Ei;
                }
            }
            __syncwarp();

            // atten_bias[g, i, c] = sum_j ( emb3[si[i,j], c] + emb4[ei[i,j], c] )
            #pragma unroll
            for (int r = 0; r < 4; r++) {
                int o = lane + 32 * r;
                if (o < VV) {
                    int i2 = o / V, c = o % V;
                    float acc = 0.0f;
                    #pragma unroll
                    for (int j2 = 0; j2 < V; j2++) {
                        acc += __ldg(&emb3[sim[w][i2 * V + j2] * V + c]);
                        acc += __ldg(&emb4[eim[w][i2 * V + j2] * V + c]);
                    }
                    out_att[(size_t)g * VV + o] = acc;
                }
            }
        }
    }
}

extern "C" void kernel_launch(void* const* d_in, const int* in_sizes, int n_in,
                              void* d_out, int out_size)
{
    const float* end_output = (const float*)d_in[0];   // (B,T,V,F)
    const float* S          = (const float*)d_in[1];   // (B,T,V,V)
    const float* mul_       = (const float*)d_in[2];   // (V,V)
    const float* bias_      = (const float*)d_in[3];   // (V,V)
    const float* means_     = (const float*)d_in[4];   // (1,V)
    const float* stds_      = (const float*)d_in[5];   // (1,V)
    const float* emb_in_    = (const float*)d_in[6];   // (F,F)
    const float* emb_out_   = (const float*)d_in[7];   // (F,F)
    const float* emb3_      = (const float*)d_in[8];   // (V,V)
    const float* emb4_      = (const float*)d_in[9];   // (V,V)

    float* out = (float*)d_out;
    const int graphs = in_sizes[1] / VV;               // B*T
    float* out_att = out + (size_t)in_sizes[0];        // atten_bias after outputs

    int nsb = (graphs + GPS - 1) / GPS;
    int ngb = (graphs + GPG - 1) / GPG;
    int total = nsb + ngb;
    int interleave = (total == 3 * ngb) ? 1 : 0;       // exact 2:1 ratio

    comb_kernel<<<V, F>>>(emb_in_, emb_out_);
    graph_embed_kernel<<<total, NT>>>(
        end_output, S, mul_, bias_, means_, stds_,
        emb3_, emb4_, out, out_att, graphs, nsb, ngb, interleave);
}